// round 1
// baseline (speedup 1.0000x reference)
#include <cuda_runtime.h>

static constexpr int H = 512;
static constexpr int W = 512;
static constexpr unsigned FULL = 0xFFFFFFFFu;

__device__ __forceinline__ float med3f(float a, float b, float c) {
    // median of 3 = max(min(a,b), min(max(a,b), c))
    return fmaxf(fminf(a, b), fminf(fmaxf(a, b), c));
}

__global__ __launch_bounds__(256)
void median3x3_kernel(const float* __restrict__ in, float* __restrict__ out, int nimg) {
    const int gwarp = (blockIdx.x * blockDim.x + threadIdx.x) >> 5;
    const int lane = threadIdx.x & 31;

    // Per image: 256 row-pairs (2 output rows each) x 4 warp-column-groups (128 cols each).
    const int img = gwarp >> 10;
    if (img >= nimg) return;
    const int rem = gwarp & 1023;
    const int y0 = (rem >> 2) << 1;                  // 0,2,...,510
    const int c0 = ((rem & 3) << 7) + (lane << 2);   // 4 columns per lane

    const float* __restrict__ base = in + (size_t)img * (H * W);
    float* __restrict__ obase = out + (size_t)img * (H * W);

    // Load 4 input rows (y0-1 .. y0+2), zero-padded at image top/bottom.
    const float4 zero4 = make_float4(0.f, 0.f, 0.f, 0.f);
    float4 r0 = (y0 > 0)     ? *(const float4*)(base + (y0 - 1) * W + c0) : zero4;
    float4 r1 =                *(const float4*)(base + (y0    ) * W + c0);
    float4 r2 =                *(const float4*)(base + (y0 + 1) * W + c0);
    float4 r3 = (y0 + 2 < H) ? *(const float4*)(base + (y0 + 2) * W + c0) : zero4;

    float A[4] = {r0.x, r0.y, r0.z, r0.w};
    float B[4] = {r1.x, r1.y, r1.z, r1.w};
    float C[4] = {r2.x, r2.y, r2.z, r2.w};
    float D[4] = {r3.x, r3.y, r3.z, r3.w};

    // Vertical sort of each column for both output rows, sharing min/max(B,C).
    float lo0[4], md0[4], hi0[4];   // sorted (A,B,C) -> output row y0
    float lo1[4], md1[4], hi1[4];   // sorted (B,C,D) -> output row y0+1
#pragma unroll
    for (int i = 0; i < 4; i++) {
        float p = fminf(B[i], C[i]);
        float q = fmaxf(B[i], C[i]);
        float m0 = fmaxf(A[i], p);
        lo0[i] = fminf(A[i], p);
        hi0[i] = fmaxf(m0, q);
        md0[i] = fminf(m0, q);
        float m1 = fmaxf(D[i], p);
        lo1[i] = fminf(D[i], p);
        hi1[i] = fmaxf(m1, q);
        md1[i] = fminf(m1, q);
    }

    // Warp-edge boundary column: lane 0 needs column c0-1, lane 31 needs c0+4.
    const bool isL = (lane == 0);
    const bool isR = (lane == 31);
    const int ecol = isL ? (c0 - 1) : (c0 + 4);
    const bool ev = (isL | isR) && ((unsigned)ecol < (unsigned)W);
    float ea = (ev && y0 > 0)     ? base[(y0 - 1) * W + ecol] : 0.f;
    float eb = ev                 ? base[(y0    ) * W + ecol] : 0.f;
    float ec = ev                 ? base[(y0 + 1) * W + ecol] : 0.f;
    float ed = (ev && y0 + 2 < H) ? base[(y0 + 2) * W + ecol] : 0.f;
    float ep = fminf(eb, ec), eq = fmaxf(eb, ec);
    float em0 = fmaxf(ea, ep);
    float elo0 = fminf(ea, ep), ehi0 = fmaxf(em0, eq), emd0 = fminf(em0, eq);
    float em1 = fmaxf(ed, ep);
    float elo1 = fminf(ed, ep), ehi1 = fmaxf(em1, eq), emd1 = fminf(em1, eq);

    // Exchange sorted-column triples with horizontal neighbors.
    float Llo0 = __shfl_up_sync(FULL, lo0[3], 1);
    float Lmd0 = __shfl_up_sync(FULL, md0[3], 1);
    float Lhi0 = __shfl_up_sync(FULL, hi0[3], 1);
    float Llo1 = __shfl_up_sync(FULL, lo1[3], 1);
    float Lmd1 = __shfl_up_sync(FULL, md1[3], 1);
    float Lhi1 = __shfl_up_sync(FULL, hi1[3], 1);
    float Rlo0 = __shfl_down_sync(FULL, lo0[0], 1);
    float Rmd0 = __shfl_down_sync(FULL, md0[0], 1);
    float Rhi0 = __shfl_down_sync(FULL, hi0[0], 1);
    float Rlo1 = __shfl_down_sync(FULL, lo1[0], 1);
    float Rmd1 = __shfl_down_sync(FULL, md1[0], 1);
    float Rhi1 = __shfl_down_sync(FULL, hi1[0], 1);
    if (isL) { Llo0 = elo0; Lmd0 = emd0; Lhi0 = ehi0; Llo1 = elo1; Lmd1 = emd1; Lhi1 = ehi1; }
    if (isR) { Rlo0 = elo0; Rmd0 = emd0; Rhi0 = ehi0; Rlo1 = elo1; Rmd1 = emd1; Rhi1 = ehi1; }

    float Lo0[6] = {Llo0, lo0[0], lo0[1], lo0[2], lo0[3], Rlo0};
    float Md0[6] = {Lmd0, md0[0], md0[1], md0[2], md0[3], Rmd0};
    float Hi0[6] = {Lhi0, hi0[0], hi0[1], hi0[2], hi0[3], Rhi0};
    float Lo1[6] = {Llo1, lo1[0], lo1[1], lo1[2], lo1[3], Rlo1};
    float Md1[6] = {Lmd1, md1[0], md1[1], md1[2], md1[3], Rmd1};
    float Hi1[6] = {Lhi1, hi1[0], hi1[1], hi1[2], hi1[3], Rhi1};

    // med9 = med3( max(col mins), med3(col meds), min(col maxes) )  -- exact identity
    float o0[4], o1[4];
#pragma unroll
    for (int i = 0; i < 4; i++) {
        float X0 = fmaxf(fmaxf(Lo0[i], Lo0[i + 1]), Lo0[i + 2]);
        float Z0 = fminf(fminf(Hi0[i], Hi0[i + 1]), Hi0[i + 2]);
        float Y0 = med3f(Md0[i], Md0[i + 1], Md0[i + 2]);
        o0[i] = med3f(X0, Y0, Z0);
        float X1 = fmaxf(fmaxf(Lo1[i], Lo1[i + 1]), Lo1[i + 2]);
        float Z1 = fminf(fminf(Hi1[i], Hi1[i + 1]), Hi1[i + 2]);
        float Y1 = med3f(Md1[i], Md1[i + 1], Md1[i + 2]);
        o1[i] = med3f(X1, Y1, Z1);
    }

    *(float4*)(obase + (y0    ) * W + c0) = make_float4(o0[0], o0[1], o0[2], o0[3]);
    *(float4*)(obase + (y0 + 1) * W + c0) = make_float4(o1[0], o1[1], o1[2], o1[3]);
}

extern "C" void kernel_launch(void* const* d_in, const int* in_sizes, int n_in,
                              void* d_out, int out_size) {
    const float* x = (const float*)d_in[0];
    float* y = (float*)d_out;
    const int nimg = in_sizes[0] / (H * W);                 // B*C images
    const int warps = nimg * (H / 2) * (W / 128);           // per-image: 256 row-pairs x 4 warp groups
    const int threads = warps * 32;
    const int block = 256;
    const int grid = (threads + block - 1) / block;
    median3x3_kernel<<<grid, block>>>(x, y, nimg);
}

// round 2
// speedup vs baseline: 1.1598x; 1.1598x over previous
#include <cuda_runtime.h>

static constexpr int H = 512;
static constexpr int W = 512;
static constexpr unsigned FULL = 0xFFFFFFFFu;

__device__ __forceinline__ float med3f(float a, float b, float c) {
    // median of 3 = max(min(a,b), min(max(a,b), c))
    return fmaxf(fminf(a, b), fminf(fmaxf(a, b), c));
}

// Merge phase for 8 outputs of one row.
// lo/md/hi are arrays of 10: [L-edge, 8 own columns, R-edge], each vertically sorted.
// Output j's window is arr[j], arr[j+1], arr[j+2]. The pair (2k+1, 2k+2) is shared
// by windows 2k and 2k+1 (min3/max3/med3 are symmetric in their arguments).
__device__ __forceinline__ void hmerge8(const float* lo, const float* md,
                                         const float* hi, float* o) {
#pragma unroll
    for (int k = 0; k < 4; k++) {
        float pxl = fmaxf(lo[2 * k + 1], lo[2 * k + 2]);   // shared max of Lo pair
        float pzl = fminf(hi[2 * k + 1], hi[2 * k + 2]);   // shared min of Hi pair
        float mn  = fminf(md[2 * k + 1], md[2 * k + 2]);   // shared sort of Md pair
        float mx  = fmaxf(md[2 * k + 1], md[2 * k + 2]);
        float X0 = fmaxf(lo[2 * k], pxl);
        float X1 = fmaxf(pxl, lo[2 * k + 3]);
        float Z0 = fminf(hi[2 * k], pzl);
        float Z1 = fminf(pzl, hi[2 * k + 3]);
        float Y0 = fmaxf(mn, fminf(mx, md[2 * k]));        // med3 via shared pair
        float Y1 = fmaxf(mn, fminf(mx, md[2 * k + 3]));
        o[2 * k]     = med3f(X0, Y0, Z0);
        o[2 * k + 1] = med3f(X1, Y1, Z1);
    }
}

__global__ __launch_bounds__(256)
void median3x3_kernel(const float* __restrict__ in, float* __restrict__ out, int nimg) {
    const int gwarp = (blockIdx.x * blockDim.x + threadIdx.x) >> 5;
    const int lane = threadIdx.x & 31;

    // Per image: 256 row-pairs (2 output rows each) x 2 warp-column-groups (256 cols each).
    const int img = gwarp >> 9;
    if (img >= nimg) return;
    const int rem = gwarp & 511;
    const int y0 = (rem >> 1) << 1;                  // 0,2,...,510
    const int c0 = ((rem & 1) << 8) + (lane << 3);   // 8 columns per lane

    const float* __restrict__ base = in + (size_t)img * (H * W);
    float* __restrict__ obase = out + (size_t)img * (H * W);

    // Load 4 input rows (y0-1 .. y0+2) x 8 columns, zero-padded at image top/bottom.
    const float4 zero4 = make_float4(0.f, 0.f, 0.f, 0.f);
    float4 r0a = (y0 > 0)     ? *(const float4*)(base + (y0 - 1) * W + c0)     : zero4;
    float4 r0b = (y0 > 0)     ? *(const float4*)(base + (y0 - 1) * W + c0 + 4) : zero4;
    float4 r1a =                *(const float4*)(base + (y0    ) * W + c0);
    float4 r1b =                *(const float4*)(base + (y0    ) * W + c0 + 4);
    float4 r2a =                *(const float4*)(base + (y0 + 1) * W + c0);
    float4 r2b =                *(const float4*)(base + (y0 + 1) * W + c0 + 4);
    float4 r3a = (y0 + 2 < H) ? *(const float4*)(base + (y0 + 2) * W + c0)     : zero4;
    float4 r3b = (y0 + 2 < H) ? *(const float4*)(base + (y0 + 2) * W + c0 + 4) : zero4;

    float A[8] = {r0a.x, r0a.y, r0a.z, r0a.w, r0b.x, r0b.y, r0b.z, r0b.w};
    float B[8] = {r1a.x, r1a.y, r1a.z, r1a.w, r1b.x, r1b.y, r1b.z, r1b.w};
    float C[8] = {r2a.x, r2a.y, r2a.z, r2a.w, r2b.x, r2b.y, r2b.z, r2b.w};
    float D[8] = {r3a.x, r3a.y, r3a.z, r3a.w, r3b.x, r3b.y, r3b.z, r3b.w};

    // Vertical sort of each column for both output rows, sharing min/max(B,C).
    float lo0[10], md0[10], hi0[10];   // sorted (A,B,C) -> output row y0   (idx 1..8 own)
    float lo1[10], md1[10], hi1[10];   // sorted (B,C,D) -> output row y0+1
#pragma unroll
    for (int i = 0; i < 8; i++) {
        float p = fminf(B[i], C[i]);
        float q = fmaxf(B[i], C[i]);
        float m0 = fmaxf(A[i], p);
        lo0[i + 1] = fminf(A[i], p);
        hi0[i + 1] = fmaxf(m0, q);
        md0[i + 1] = fminf(m0, q);
        float m1 = fmaxf(D[i], p);
        lo1[i + 1] = fminf(D[i], p);
        hi1[i + 1] = fmaxf(m1, q);
        md1[i + 1] = fminf(m1, q);
    }

    // Warp-edge boundary column: lane 0 needs column c0-1, lane 31 needs c0+8.
    const bool isL = (lane == 0);
    const bool isR = (lane == 31);
    const int ecol = isL ? (c0 - 1) : (c0 + 8);
    const bool ev = (isL | isR) && ((unsigned)ecol < (unsigned)W);
    float ea = (ev && y0 > 0)     ? base[(y0 - 1) * W + ecol] : 0.f;
    float eb = ev                 ? base[(y0    ) * W + ecol] : 0.f;
    float ec = ev                 ? base[(y0 + 1) * W + ecol] : 0.f;
    float ed = (ev && y0 + 2 < H) ? base[(y0 + 2) * W + ecol] : 0.f;
    float ep = fminf(eb, ec), eq = fmaxf(eb, ec);
    float em0 = fmaxf(ea, ep);
    float elo0 = fminf(ea, ep), ehi0 = fmaxf(em0, eq), emd0 = fminf(em0, eq);
    float em1 = fmaxf(ed, ep);
    float elo1 = fminf(ed, ep), ehi1 = fmaxf(em1, eq), emd1 = fminf(em1, eq);

    // Exchange sorted-column triples with horizontal neighbors.
    float Llo0 = __shfl_up_sync(FULL, lo0[8], 1);
    float Lmd0 = __shfl_up_sync(FULL, md0[8], 1);
    float Lhi0 = __shfl_up_sync(FULL, hi0[8], 1);
    float Llo1 = __shfl_up_sync(FULL, lo1[8], 1);
    float Lmd1 = __shfl_up_sync(FULL, md1[8], 1);
    float Lhi1 = __shfl_up_sync(FULL, hi1[8], 1);
    float Rlo0 = __shfl_down_sync(FULL, lo0[1], 1);
    float Rmd0 = __shfl_down_sync(FULL, md0[1], 1);
    float Rhi0 = __shfl_down_sync(FULL, hi0[1], 1);
    float Rlo1 = __shfl_down_sync(FULL, lo1[1], 1);
    float Rmd1 = __shfl_down_sync(FULL, md1[1], 1);
    float Rhi1 = __shfl_down_sync(FULL, hi1[1], 1);
    if (isL) { Llo0 = elo0; Lmd0 = emd0; Lhi0 = ehi0; Llo1 = elo1; Lmd1 = emd1; Lhi1 = ehi1; }
    if (isR) { Rlo0 = elo0; Rmd0 = emd0; Rhi0 = ehi0; Rlo1 = elo1; Rmd1 = emd1; Rhi1 = ehi1; }

    lo0[0] = Llo0; md0[0] = Lmd0; hi0[0] = Lhi0;
    lo1[0] = Llo1; md1[0] = Lmd1; hi1[0] = Lhi1;
    lo0[9] = Rlo0; md0[9] = Rmd0; hi0[9] = Rhi0;
    lo1[9] = Rlo1; md1[9] = Rmd1; hi1[9] = Rhi1;

    float o0[8], o1[8];
    hmerge8(lo0, md0, hi0, o0);
    hmerge8(lo1, md1, hi1, o1);

    *(float4*)(obase + (y0    ) * W + c0)     = make_float4(o0[0], o0[1], o0[2], o0[3]);
    *(float4*)(obase + (y0    ) * W + c0 + 4) = make_float4(o0[4], o0[5], o0[6], o0[7]);
    *(float4*)(obase + (y0 + 1) * W + c0)     = make_float4(o1[0], o1[1], o1[2], o1[3]);
    *(float4*)(obase + (y0 + 1) * W + c0 + 4) = make_float4(o1[4], o1[5], o1[6], o1[7]);
}

extern "C" void kernel_launch(void* const* d_in, const int* in_sizes, int n_in,
                              void* d_out, int out_size) {
    const float* x = (const float*)d_in[0];
    float* y = (float*)d_out;
    const int nimg = in_sizes[0] / (H * W);                 // B*C images
    const int warps = nimg * (H / 2) * (W / 256);           // per-image: 256 row-pairs x 2 groups
    const int threads = warps * 32;
    const int block = 256;
    const int grid = (threads + block - 1) / block;
    median3x3_kernel<<<grid, block>>>(x, y, nimg);
}

// round 4
// speedup vs baseline: 1.2232x; 1.0547x over previous
#include <cuda_runtime.h>

static constexpr int H = 512;
static constexpr int W = 512;
static constexpr unsigned FULL = 0xFFFFFFFFu;

__device__ __forceinline__ float med3f(float a, float b, float c) {
    return fmaxf(fminf(a, b), fminf(fmaxf(a, b), c));
}

// Horizontal merge for 8 outputs of one row.
// lo/md/hi: [L-edge, 8 own columns, R-edge], each vertically sorted.
// Pair (2k+1, 2k+2) is shared by windows 2k and 2k+1.
__device__ __forceinline__ void hmerge8(const float* lo, const float* md,
                                         const float* hi, float* o) {
#pragma unroll
    for (int k = 0; k < 4; k++) {
        float pxl = fmaxf(lo[2 * k + 1], lo[2 * k + 2]);
        float pzl = fminf(hi[2 * k + 1], hi[2 * k + 2]);
        float mn  = fminf(md[2 * k + 1], md[2 * k + 2]);
        float mx  = fmaxf(md[2 * k + 1], md[2 * k + 2]);
        float X0 = fmaxf(lo[2 * k], pxl);
        float X1 = fmaxf(pxl, lo[2 * k + 3]);
        float Z0 = fminf(hi[2 * k], pzl);
        float Z1 = fminf(pzl, hi[2 * k + 3]);
        float Y0 = fmaxf(mn, fminf(mx, md[2 * k]));
        float Y1 = fmaxf(mn, fminf(mx, md[2 * k + 3]));
        o[2 * k]     = med3f(X0, Y0, Z0);
        o[2 * k + 1] = med3f(X1, Y1, Z1);
    }
}

__global__ __launch_bounds__(256, 4)
void median3x3_kernel(const float* __restrict__ in, float* __restrict__ out, int nimg) {
    const int gwarp = (blockIdx.x * blockDim.x + threadIdx.x) >> 5;
    const int lane = threadIdx.x & 31;

    // Per image: 256 row-pairs x 2 warp-column-groups (256 cols each).
    const int img = gwarp >> 9;
    if (img >= nimg) return;
    const int rem = gwarp & 511;
    const int y0 = (rem >> 1) << 1;                  // 0,2,...,510
    const int c0 = ((rem & 1) << 8) + (lane << 3);   // 8 columns per lane

    const float* __restrict__ base = in + (size_t)img * (H * W);
    float* __restrict__ obase = out + (size_t)img * (H * W);

    // ---- All loads issued up front (max MLP): 8 x LDG.128 + 4 edge scalars ----
    const float4 zero4 = make_float4(0.f, 0.f, 0.f, 0.f);
    float4 r0a = (y0 > 0)     ? *(const float4*)(base + (y0 - 1) * W + c0)     : zero4;
    float4 r0b = (y0 > 0)     ? *(const float4*)(base + (y0 - 1) * W + c0 + 4) : zero4;
    float4 r1a =                *(const float4*)(base + (y0    ) * W + c0);
    float4 r1b =                *(const float4*)(base + (y0    ) * W + c0 + 4);
    float4 r2a =                *(const float4*)(base + (y0 + 1) * W + c0);
    float4 r2b =                *(const float4*)(base + (y0 + 1) * W + c0 + 4);
    float4 r3a = (y0 + 2 < H) ? *(const float4*)(base + (y0 + 2) * W + c0)     : zero4;
    float4 r3b = (y0 + 2 < H) ? *(const float4*)(base + (y0 + 2) * W + c0 + 4) : zero4;

    const bool isL = (lane == 0);
    const bool isR = (lane == 31);
    const int ecol = isL ? (c0 - 1) : (c0 + 8);
    const bool ev = (isL | isR) && ((unsigned)ecol < (unsigned)W);
    float ea = (ev && y0 > 0)     ? base[(y0 - 1) * W + ecol] : 0.f;
    float eb = ev                 ? base[(y0    ) * W + ecol] : 0.f;
    float ec = ev                 ? base[(y0 + 1) * W + ecol] : 0.f;
    float ed = (ev && y0 + 2 < H) ? base[(y0 + 2) * W + ecol] : 0.f;

    // ---- Shared vertical pair p,q = sort(rowB, rowC); rows B,C die here ----
    float A[8] = {r0a.x, r0a.y, r0a.z, r0a.w, r0b.x, r0b.y, r0b.z, r0b.w};
    float Dr[8] = {r3a.x, r3a.y, r3a.z, r3a.w, r3b.x, r3b.y, r3b.z, r3b.w};
    float p[8], q[8];
    {
        float Bv[8] = {r1a.x, r1a.y, r1a.z, r1a.w, r1b.x, r1b.y, r1b.z, r1b.w};
        float Cv[8] = {r2a.x, r2a.y, r2a.z, r2a.w, r2b.x, r2b.y, r2b.z, r2b.w};
#pragma unroll
        for (int i = 0; i < 8; i++) {
            p[i] = fminf(Bv[i], Cv[i]);
            q[i] = fmaxf(Bv[i], Cv[i]);
        }
    }
    const float ep = fminf(eb, ec);
    const float eq = fmaxf(eb, ec);

    float lo[10], md[10], hi[10];
    float o[8];

    // ================= Output row y0 : triple = sort(A, p, q) =================
#pragma unroll
    for (int i = 0; i < 8; i++) {
        float m = fmaxf(A[i], p[i]);
        lo[i + 1] = fminf(A[i], p[i]);
        hi[i + 1] = fmaxf(m, q[i]);
        md[i + 1] = fminf(m, q[i]);
    }
    {
        float em = fmaxf(ea, ep);
        float elo = fminf(ea, ep), ehi = fmaxf(em, eq), emd = fminf(em, eq);
        float Ll = __shfl_up_sync(FULL, lo[8], 1);
        float Lm = __shfl_up_sync(FULL, md[8], 1);
        float Lh = __shfl_up_sync(FULL, hi[8], 1);
        float Rl = __shfl_down_sync(FULL, lo[1], 1);
        float Rm = __shfl_down_sync(FULL, md[1], 1);
        float Rh = __shfl_down_sync(FULL, hi[1], 1);
        lo[0] = isL ? elo : Ll;  md[0] = isL ? emd : Lm;  hi[0] = isL ? ehi : Lh;
        lo[9] = isR ? elo : Rl;  md[9] = isR ? emd : Rm;  hi[9] = isR ? ehi : Rh;
    }
    hmerge8(lo, md, hi, o);
    *(float4*)(obase + y0 * W + c0)     = make_float4(o[0], o[1], o[2], o[3]);
    *(float4*)(obase + y0 * W + c0 + 4) = make_float4(o[4], o[5], o[6], o[7]);

    // ================= Output row y0+1 : triple = sort(D, p, q) =================
#pragma unroll
    for (int i = 0; i < 8; i++) {
        float m = fmaxf(Dr[i], p[i]);
        lo[i + 1] = fminf(Dr[i], p[i]);
        hi[i + 1] = fmaxf(m, q[i]);
        md[i + 1] = fminf(m, q[i]);
    }
    {
        float em = fmaxf(ed, ep);
        float elo = fminf(ed, ep), ehi = fmaxf(em, eq), emd = fminf(em, eq);
        float Ll = __shfl_up_sync(FULL, lo[8], 1);
        float Lm = __shfl_up_sync(FULL, md[8], 1);
        float Lh = __shfl_up_sync(FULL, hi[8], 1);
        float Rl = __shfl_down_sync(FULL, lo[1], 1);
        float Rm = __shfl_down_sync(FULL, md[1], 1);
        float Rh = __shfl_down_sync(FULL, hi[1], 1);
        lo[0] = isL ? elo : Ll;  md[0] = isL ? emd : Lm;  hi[0] = isL ? ehi : Lh;
        lo[9] = isR ? elo : Rl;  md[9] = isR ? emd : Rm;  hi[9] = isR ? ehi : Rh;
    }
    hmerge8(lo, md, hi, o);
    *(float4*)(obase + (y0 + 1) * W + c0)     = make_float4(o[0], o[1], o[2], o[3]);
    *(float4*)(obase + (y0 + 1) * W + c0 + 4) = make_float4(o[4], o[5], o[6], o[7]);
}

extern "C" void kernel_launch(void* const* d_in, const int* in_sizes, int n_in,
                              void* d_out, int out_size) {
    const float* x = (const float*)d_in[0];
    float* y = (float*)d_out;
    const int nimg = in_sizes[0] / (H * W);                 // B*C images
    const int warps = nimg * (H / 2) * (W / 256);           // per-image: 256 row-pairs x 2 groups
    const int threads = warps * 32;
    const int block = 256;
    const int grid = (threads + block - 1) / block;
    median3x3_kernel<<<grid, block>>>(x, y, nimg);
}

// round 5
// speedup vs baseline: 1.3358x; 1.0920x over previous
#include <cuda_runtime.h>

static constexpr int H = 512;
static constexpr int W = 512;
static constexpr unsigned FULL = 0xFFFFFFFFu;

__device__ __forceinline__ float med3f(float a, float b, float c) {
    return fmaxf(fminf(a, b), fminf(fmaxf(a, b), c));
}

// Horizontal merge for 8 outputs of one row.
// lo/md/hi: [L-edge, 8 own columns, R-edge], each vertically sorted.
// Pair (2k+1, 2k+2) is shared by windows 2k and 2k+1.
__device__ __forceinline__ void hmerge8(const float* lo, const float* md,
                                         const float* hi, float* o) {
#pragma unroll
    for (int k = 0; k < 4; k++) {
        float pxl = fmaxf(lo[2 * k + 1], lo[2 * k + 2]);
        float pzl = fminf(hi[2 * k + 1], hi[2 * k + 2]);
        float mn  = fminf(md[2 * k + 1], md[2 * k + 2]);
        float mx  = fmaxf(md[2 * k + 1], md[2 * k + 2]);
        float X0 = fmaxf(lo[2 * k], pxl);
        float X1 = fmaxf(pxl, lo[2 * k + 3]);
        float Z0 = fminf(hi[2 * k], pzl);
        float Z1 = fminf(pzl, hi[2 * k + 3]);
        float Y0 = fmaxf(mn, fminf(mx, md[2 * k]));
        float Y1 = fmaxf(mn, fminf(mx, md[2 * k + 3]));
        o[2 * k]     = med3f(X0, Y0, Z0);
        o[2 * k + 1] = med3f(X1, Y1, Z1);
    }
}

// Build triple (t merged into pre-sorted pair p,q), exchange edges, merge, store one row.
__device__ __forceinline__ void do_row(const float* t, const float* p, const float* q,
                                        float et, float ep, float eq,
                                        bool isL, bool isR,
                                        float* __restrict__ orow, int c0) {
    float lo[10], md[10], hi[10];
#pragma unroll
    for (int i = 0; i < 8; i++) {
        float m = fmaxf(t[i], p[i]);
        lo[i + 1] = fminf(t[i], p[i]);
        hi[i + 1] = fmaxf(m, q[i]);
        md[i + 1] = fminf(m, q[i]);
    }
    float em = fmaxf(et, ep);
    float elo = fminf(et, ep), ehi = fmaxf(em, eq), emd = fminf(em, eq);
    float Ll = __shfl_up_sync(FULL, lo[8], 1);
    float Lm = __shfl_up_sync(FULL, md[8], 1);
    float Lh = __shfl_up_sync(FULL, hi[8], 1);
    float Rl = __shfl_down_sync(FULL, lo[1], 1);
    float Rm = __shfl_down_sync(FULL, md[1], 1);
    float Rh = __shfl_down_sync(FULL, hi[1], 1);
    lo[0] = isL ? elo : Ll;  md[0] = isL ? emd : Lm;  hi[0] = isL ? ehi : Lh;
    lo[9] = isR ? elo : Rl;  md[9] = isR ? emd : Rm;  hi[9] = isR ? ehi : Rh;
    float o[8];
    hmerge8(lo, md, hi, o);
    *(float4*)(orow + c0)     = make_float4(o[0], o[1], o[2], o[3]);
    *(float4*)(orow + c0 + 4) = make_float4(o[4], o[5], o[6], o[7]);
}

__global__ __launch_bounds__(128, 6)
void median3x3_kernel(const float* __restrict__ in, float* __restrict__ out, int nimg) {
    const int gwarp = (blockIdx.x * blockDim.x + threadIdx.x) >> 5;
    const int lane = threadIdx.x & 31;

    // Per image: 128 row-quads (4 output rows each) x 2 warp-column-groups (256 cols each).
    const int img = gwarp >> 8;
    if (img >= nimg) return;
    const int rem = gwarp & 255;
    const int y0 = (rem >> 1) << 2;                  // 0,4,...,508
    const int c0 = ((rem & 1) << 8) + (lane << 3);   // 8 columns per lane

    const float* __restrict__ base = in + (size_t)img * (H * W);
    float* __restrict__ obase = out + (size_t)img * (H * W);

    // ---- Load 6 input rows (y0-1 .. y0+4) x 8 cols: 12 x LDG.128, max MLP ----
    const float4 zero4 = make_float4(0.f, 0.f, 0.f, 0.f);
    float4 i0a = (y0 > 0)     ? *(const float4*)(base + (y0 - 1) * W + c0)     : zero4;
    float4 i0b = (y0 > 0)     ? *(const float4*)(base + (y0 - 1) * W + c0 + 4) : zero4;
    float4 i1a =                *(const float4*)(base + (y0    ) * W + c0);
    float4 i1b =                *(const float4*)(base + (y0    ) * W + c0 + 4);
    float4 i2a =                *(const float4*)(base + (y0 + 1) * W + c0);
    float4 i2b =                *(const float4*)(base + (y0 + 1) * W + c0 + 4);
    float4 i3a =                *(const float4*)(base + (y0 + 2) * W + c0);
    float4 i3b =                *(const float4*)(base + (y0 + 2) * W + c0 + 4);
    float4 i4a =                *(const float4*)(base + (y0 + 3) * W + c0);
    float4 i4b =                *(const float4*)(base + (y0 + 3) * W + c0 + 4);
    float4 i5a = (y0 + 4 < H) ? *(const float4*)(base + (y0 + 4) * W + c0)     : zero4;
    float4 i5b = (y0 + 4 < H) ? *(const float4*)(base + (y0 + 4) * W + c0 + 4) : zero4;

    // Warp-edge boundary column (6 rows), lanes 0/31 only.
    const bool isL = (lane == 0);
    const bool isR = (lane == 31);
    const int ecol = isL ? (c0 - 1) : (c0 + 8);
    const bool ev = (isL | isR) && ((unsigned)ecol < (unsigned)W);
    float e0 = (ev && y0 > 0)     ? base[(y0 - 1) * W + ecol] : 0.f;
    float e1 = ev                 ? base[(y0    ) * W + ecol] : 0.f;
    float e2 = ev                 ? base[(y0 + 1) * W + ecol] : 0.f;
    float e3 = ev                 ? base[(y0 + 2) * W + ecol] : 0.f;
    float e4 = ev                 ? base[(y0 + 3) * W + ecol] : 0.f;
    float e5 = (ev && y0 + 4 < H) ? base[(y0 + 4) * W + ecol] : 0.f;

    float t0[8] = {i0a.x, i0a.y, i0a.z, i0a.w, i0b.x, i0b.y, i0b.z, i0b.w};
    float r2[8] = {i2a.x, i2a.y, i2a.z, i2a.w, i2b.x, i2b.y, i2b.z, i2b.w};
    float r3[8] = {i3a.x, i3a.y, i3a.z, i3a.w, i3b.x, i3b.y, i3b.z, i3b.w};
    float r4[8] = {i4a.x, i4a.y, i4a.z, i4a.w, i4b.x, i4b.y, i4b.z, i4b.w};
    float t5[8] = {i5a.x, i5a.y, i5a.z, i5a.w, i5b.x, i5b.y, i5b.z, i5b.w};

    // ---- Pair A = sort(i1, i2); i1 dies, i2 kept raw for row o2 ----
    float p[8], q[8];
    {
        float r1[8] = {i1a.x, i1a.y, i1a.z, i1a.w, i1b.x, i1b.y, i1b.z, i1b.w};
#pragma unroll
        for (int i = 0; i < 8; i++) {
            p[i] = fminf(r1[i], r2[i]);
            q[i] = fmaxf(r1[i], r2[i]);
        }
    }
    float epA = fminf(e1, e2), eqA = fmaxf(e1, e2);

    // Rows o0 = (i0, i1, i2), o1 = (i1, i2, i3) via shared pair A.
    do_row(t0, p, q, e0, epA, eqA, isL, isR, obase + (y0    ) * W, c0);
    do_row(r3, p, q, e3, epA, eqA, isL, isR, obase + (y0 + 1) * W, c0);

    // ---- Pair B = sort(i3, i4); reuse p,q storage ----
#pragma unroll
    for (int i = 0; i < 8; i++) {
        float mn = fminf(r3[i], r4[i]);
        float mx = fmaxf(r3[i], r4[i]);
        p[i] = mn;
        q[i] = mx;
    }
    float epB = fminf(e3, e4), eqB = fmaxf(e3, e4);

    // Rows o2 = (i2, i3, i4), o3 = (i3, i4, i5) via shared pair B.
    do_row(r2, p, q, e2, epB, eqB, isL, isR, obase + (y0 + 2) * W, c0);
    do_row(t5, p, q, e5, epB, eqB, isL, isR, obase + (y0 + 3) * W, c0);
}

extern "C" void kernel_launch(void* const* d_in, const int* in_sizes, int n_in,
                              void* d_out, int out_size) {
    const float* x = (const float*)d_in[0];
    float* y = (float*)d_out;
    const int nimg = in_sizes[0] / (H * W);                  // B*C images
    const int warps = nimg * (H / 4) * (W / 256);            // 128 row-quads x 2 groups
    const int threads = warps * 32;
    const int block = 128;
    const int grid = (threads + block - 1) / block;
    median3x3_kernel<<<grid, block>>>(x, y, nimg);
}